// round 14
// baseline (speedup 1.0000x reference)
#include <cuda_runtime.h>
#include <cuda_bf16.h>
#include <math.h>

using ull = unsigned long long;
using bf = __nv_bfloat16;

constexpr int B_   = 32;
constexpr int C_   = 64;
constexpr int L_   = 512;
constexpr int NP_  = 125;
constexpr int D_   = 128;
constexpr int INNER_ = 256;
constexpr int M_   = B_ * NP_;    // 4000
constexpr int CF_  = 6144;        // C*F
constexpr int DNP_ = 16000;       // D*NP
constexpr int KS_  = 25;          // split-K for final GEMM (640 k each)
constexpr float EPS_ = 1e-5f;

// weight slab offsets (bf16 hi/lo converted once per launch)
constexpr int WOFF_EMB = 0;                 // 128 x 1024
constexpr int WSZ_EMB  = 128 * 1024;
constexpr int WSZ_LAYER = 2 * 256 * 128 + 128 * 256;  // ipa+ipb + op = 98304
constexpr int WTOT = WSZ_EMB + 4 * WSZ_LAYER;         // 524288
constexpr int PREP_TOT = WTOT + NP_ * D_;             // + PE table

// dynamic smem sizes
constexpr int SM_EMB = 25600 * 2;             // 50 KB  (double-buffered chunks)
constexpr int SM_IP  = 43520 * 2;             // 85 KB  (full K=128 resident)
constexpr int SM_OP  = 84480 * 2;             // 165 KB (full K=256 resident)
constexpr int SM_FIN = 2 * 32 * 648 * 2;      // 83 KB  (two 640-k act slabs)

// -------- device scratch (no allocation allowed) --------
__device__ float g_h[M_ * D_];          // hidden (fp32, residual base)
__device__ float g_scale[M_];           // rmsnorm scale per row
__device__ float g_a[M_ * INNER_];      // in-proj a
__device__ float g_bv[M_ * INNER_];     // in-proj b
__device__ float g_u[M_ * INNER_];      // gated scan out
__device__ float g_part[KS_ * B_ * CF_];// split-K partials
__device__ float g_pe[NP_ * D_];        // accurate sincos PE table
__device__ bf g_fhi[B_ * DNP_];         // normalized flat, bf16 hi
__device__ bf g_flo[B_ * DNP_];         // normalized flat, bf16 lo
__device__ bf g_nhh[M_ * D_];           // normalized hidden, bf16 hi
__device__ bf g_nhl[M_ * D_];           // normalized hidden, bf16 lo
__device__ bf g_wbh[WTOT];              // weights bf16 hi
__device__ bf g_wbl[WTOT];              // weights bf16 lo

__device__ __forceinline__ void cp16(unsigned s, const void* g) {
    asm volatile("cp.async.cg.shared.global [%0],[%1],16;" :: "r"(s), "l"(g));
}
__device__ __forceinline__ void cp_commit() { asm volatile("cp.async.commit_group;"); }
__device__ __forceinline__ void cp_waitall() { asm volatile("cp.async.wait_group 0;" ::: "memory"); }
template<int N>
__device__ __forceinline__ void cp_waitg() { asm volatile("cp.async.wait_group %0;" :: "n"(N) : "memory"); }

__device__ __forceinline__ void mma_bf16(float* c, const unsigned* a,
                                         unsigned b0, unsigned b1) {
    asm volatile(
        "mma.sync.aligned.m16n8k16.row.col.f32.bf16.bf16.f32 "
        "{%0,%1,%2,%3}, {%4,%5,%6,%7}, {%8,%9}, {%0,%1,%2,%3};"
        : "+f"(c[0]), "+f"(c[1]), "+f"(c[2]), "+f"(c[3])
        : "r"(a[0]), "r"(a[1]), "r"(a[2]), "r"(a[3]), "r"(b0), "r"(b1));
}
__device__ __forceinline__ unsigned ldu32(const bf* p) {
    return *reinterpret_cast<const unsigned*>(p);
}
__device__ __forceinline__ void split_bf(float v, bf& h, bf& l) {
    h = __float2bfloat16(v);
    l = __float2bfloat16(v - __bfloat162float(h));
}

// =====================================================================
// Kernel 0: merged prep — weight slabs (bf16 hi/lo) + PE table.
// =====================================================================
__global__ __launch_bounds__(256) void k_prep_all(const float* __restrict__ peW,
                                                  const float* __restrict__ normw,
                                                  const float* __restrict__ ipaW,
                                                  const float* __restrict__ ipbW,
                                                  const float* __restrict__ opW) {
    int idx = blockIdx.x * 256 + threadIdx.x;
    if (idx >= PREP_TOT) return;
    if (idx >= WTOT) {
        int p = idx - WTOT;
        int kq = p >> 7, col = p & 127;
        int ii = col >> 1;
        float targ = (-9.210340371976184f) * (float)ii * (1.0f / 64.0f);
        float divf = (float)exp((double)targ);
        float ang = (float)kq * divf;
        double a = (double)ang;
        g_pe[p] = (float)((col & 1) ? cos(a) : sin(a));
        return;
    }
    float v;
    if (idx < WSZ_EMB) {
        v = peW[idx];
    } else {
        int r = idx - WSZ_EMB;
        int l = r / WSZ_LAYER;
        int o = r - l * WSZ_LAYER;
        if (o < 32768)       v = ipaW[l * 32768 + o] * normw[l * 128 + (o & 127)];
        else if (o < 65536)  v = ipbW[l * 32768 + (o - 32768)] * normw[l * 128 + (o & 127)];
        else                 v = opW[l * 32768 + (o - 65536)];
    }
    bf h, l2; split_bf(v, h, l2);
    g_wbh[idx] = h;
    g_wbl[idx] = l2;
}

// =====================================================================
// Kernel 1: patch-embed GEMM, double-buffered chunks (dyn smem 50KB).
// =====================================================================
__global__ __launch_bounds__(256) void k_embed(const float* __restrict__ x,
                                               const float* __restrict__ peb) {
    extern __shared__ __align__(16) bf sm[];
    const int t = threadIdx.x, lane = t & 31, w = t >> 5;
    const int mg = w >> 2, nq = w & 3;
    const int growb = blockIdx.x * 32;

    auto stage = [&](int kch, int buf) {
        bf* ah = sm + buf * 1280;
        bf* al = sm + 2560 + buf * 1280;
#pragma unroll
        for (int q = 0; q < 4; q++) {
            int idx = t + 256 * q;
            int row = idx >> 5, kk = idx & 31;
            int gk = kch * 32 + kk, c = gk >> 4, p = gk & 15;
            int grow = growb + row, bb = grow / 125, kq = grow - bb * 125;
            float v = x[(bb * C_ + c) * L_ + kq * 4 + p];
            split_bf(v, ah[row * 40 + kk], al[row * 40 + kk]);
        }
        unsigned whb = (unsigned)__cvta_generic_to_shared(sm + 5120 + buf * 5120);
        unsigned wlb = (unsigned)__cvta_generic_to_shared(sm + 15360 + buf * 5120);
#pragma unroll
        for (int q = 0; q < 2; q++) {
            int idx = t + 256 * q;
            int row = idx >> 2, k4 = idx & 3;
            cp16(whb + row * 80 + k4 * 16, g_wbh + WOFF_EMB + row * 1024 + kch * 32 + k4 * 8);
            cp16(wlb + row * 80 + k4 * 16, g_wbl + WOFF_EMB + row * 1024 + kch * 32 + k4 * 8);
        }
        cp_commit();
    };

    float acc[4][4] = {};
    stage(0, 0);

    for (int kch = 0; kch < 32; kch++) {
        const int buf = kch & 1;
        cp_waitall();
        __syncthreads();
        if (kch + 1 < 32) stage(kch + 1, buf ^ 1);

        const bf* ah = sm + buf * 1280;
        const bf* al = sm + 2560 + buf * 1280;
        const bf* wh = sm + 5120 + buf * 5120;
        const bf* wl = sm + 15360 + buf * 5120;
#pragma unroll
        for (int kst = 0; kst < 2; kst++) {
            const int ko = kst * 16 + 2 * (lane & 3);
            const int r0 = mg * 16 + (lane >> 2);
            unsigned af[4], alf[4];
            af[0] = ldu32(&ah[r0 * 40 + ko]);       af[1] = ldu32(&ah[(r0 + 8) * 40 + ko]);
            af[2] = ldu32(&ah[r0 * 40 + ko + 8]);   af[3] = ldu32(&ah[(r0 + 8) * 40 + ko + 8]);
            alf[0] = ldu32(&al[r0 * 40 + ko]);      alf[1] = ldu32(&al[(r0 + 8) * 40 + ko]);
            alf[2] = ldu32(&al[r0 * 40 + ko + 8]);  alf[3] = ldu32(&al[(r0 + 8) * 40 + ko + 8]);
#pragma unroll
            for (int nt = 0; nt < 4; nt++) {
                int n = nq * 32 + nt * 8 + (lane >> 2);
                unsigned bh0 = ldu32(&wh[n * 40 + ko]), bh1 = ldu32(&wh[n * 40 + ko + 8]);
                unsigned bl0 = ldu32(&wl[n * 40 + ko]), bl1 = ldu32(&wl[n * 40 + ko + 8]);
                mma_bf16(acc[nt], af, bh0, bh1);
                mma_bf16(acc[nt], af, bl0, bl1);
                mma_bf16(acc[nt], alf, bh0, bh1);
            }
        }
        __syncthreads();
    }

    float (*hbuf)[132] = reinterpret_cast<float(*)[132]>(sm);
#pragma unroll
    for (int nt = 0; nt < 4; nt++) {
        int colw = nq * 32 + nt * 8 + 2 * (lane & 3);
        int r0 = mg * 16 + (lane >> 2);
        *reinterpret_cast<float2*>(&hbuf[r0][colw]) = make_float2(acc[nt][0], acc[nt][1]);
        *reinterpret_cast<float2*>(&hbuf[r0 + 8][colw]) = make_float2(acc[nt][2], acc[nt][3]);
    }
    __syncthreads();

    {
        int row = t >> 3, part = t & 7;
        int grow = growb + row, bb = grow / 125, kq = grow - bb * 125;
        float ssq = 0.f;
#pragma unroll
        for (int j = 0; j < 16; j++) {
            int c = part * 16 + j;
            float v = hbuf[row][c] + peb[c] + g_pe[kq * 128 + c];
            hbuf[row][c] = v;
            ssq += v * v;
        }
        ssq += __shfl_xor_sync(0xffffffffu, ssq, 1);
        ssq += __shfl_xor_sync(0xffffffffu, ssq, 2);
        ssq += __shfl_xor_sync(0xffffffffu, ssq, 4);
        float sc = rsqrtf(ssq * (1.0f / 128.0f) + EPS_);
        if (part == 0) g_scale[grow] = sc;
#pragma unroll
        for (int j = 0; j < 16; j += 2) {
            int c = part * 16 + j;
            float v0 = hbuf[row][c], v1 = hbuf[row][c + 1];
            *reinterpret_cast<float2*>(&g_h[grow * 128 + c]) = make_float2(v0, v1);
            bf h0, l0, h1, l1;
            split_bf(v0 * sc, h0, l0); split_bf(v1 * sc, h1, l1);
            bf hp[2] = {h0, h1}, lp[2] = {l0, l1};
            *reinterpret_cast<unsigned*>(&g_nhh[grow * 128 + c]) = *reinterpret_cast<unsigned*>(hp);
            *reinterpret_cast<unsigned*>(&g_nhl[grow * 128 + c]) = *reinterpret_cast<unsigned*>(lp);
        }
    }
}

// =====================================================================
// Kernel 2: in-projections — full K=128 resident; two K-half commit
// groups + wait-ladder (fill overlaps first half's MMAs).
// =====================================================================
__global__ __launch_bounds__(256) void k_inproj(int lbase) {
    extern __shared__ __align__(16) bf sm[];
    bf* ah = sm;            bf* al = sm + 4352;
    bf* wh = sm + 8704;     bf* wl = sm + 26112;
    const int t = threadIdx.x, lane = t & 31, w = t >> 5;
    const int mg = w >> 2, nq = w & 3;
    const int growb = blockIdx.x * 32;
    const int ny = blockIdx.y;
    const int woff = lbase + ny * 128 * 128;

    const unsigned ahb = (unsigned)__cvta_generic_to_shared(ah);
    const unsigned alb = (unsigned)__cvta_generic_to_shared(al);
    const unsigned whb = (unsigned)__cvta_generic_to_shared(wh);
    const unsigned wlb = (unsigned)__cvta_generic_to_shared(wl);

#pragma unroll
    for (int gsel = 0; gsel < 2; gsel++) {
#pragma unroll
        for (int q = 0; q < 2; q++) {
            int idx = t + 256 * q;
            int sl = idx >> 8;
            int c = idx & 255;
            int row = c >> 3, k4 = (c & 7) + gsel * 8;
            cp16((sl ? alb : ahb) + row * 272 + k4 * 16,
                 (sl ? g_nhl : g_nhh) + (growb + row) * 128 + k4 * 8);
        }
#pragma unroll
        for (int q = 0; q < 8; q++) {
            int idx = t + 256 * q;
            int sl = idx >> 10;
            int c = idx & 1023;
            int row = c >> 3, k4 = (c & 7) + gsel * 8;
            cp16((sl ? wlb : whb) + row * 272 + k4 * 16,
                 (sl ? g_wbl : g_wbh) + woff + row * 128 + k4 * 8);
        }
        cp_commit();
    }

    float acc[4][4] = {};
#pragma unroll
    for (int half = 0; half < 2; half++) {
        if (half == 0) cp_waitg<1>(); else cp_waitg<0>();
        __syncthreads();
#pragma unroll
        for (int ks2 = 0; ks2 < 4; ks2++) {
            int kst = half * 4 + ks2;
            const int ko = kst * 16 + 2 * (lane & 3);
            const int r0 = mg * 16 + (lane >> 2);
            unsigned af[4], alf[4];
            af[0] = ldu32(&ah[r0 * 136 + ko]);       af[1] = ldu32(&ah[(r0 + 8) * 136 + ko]);
            af[2] = ldu32(&ah[r0 * 136 + ko + 8]);   af[3] = ldu32(&ah[(r0 + 8) * 136 + ko + 8]);
            alf[0] = ldu32(&al[r0 * 136 + ko]);      alf[1] = ldu32(&al[(r0 + 8) * 136 + ko]);
            alf[2] = ldu32(&al[r0 * 136 + ko + 8]);  alf[3] = ldu32(&al[(r0 + 8) * 136 + ko + 8]);
#pragma unroll
            for (int nt = 0; nt < 4; nt++) {
                int n = nq * 32 + nt * 8 + (lane >> 2);
                unsigned bh0 = ldu32(&wh[n * 136 + ko]), bh1 = ldu32(&wh[n * 136 + ko + 8]);
                unsigned bl0 = ldu32(&wl[n * 136 + ko]), bl1 = ldu32(&wl[n * 136 + ko + 8]);
                mma_bf16(acc[nt], af, bh0, bh1);
                mma_bf16(acc[nt], af, bl0, bl1);
                mma_bf16(acc[nt], alf, bh0, bh1);
            }
        }
    }

    float* out = (ny < 2) ? g_a : g_bv;
    const int colb = (ny & 1) * 128;
#pragma unroll
    for (int nt = 0; nt < 4; nt++) {
        int col = colb + nq * 32 + nt * 8 + 2 * (lane & 3);
        int r0 = growb + mg * 16 + (lane >> 2);
        *reinterpret_cast<float2*>(&out[r0 * INNER_ + col]) = make_float2(acc[nt][0], acc[nt][1]);
        *reinterpret_cast<float2*>(&out[(r0 + 8) * INNER_ + col]) = make_float2(acc[nt][2], acc[nt][3]);
    }
}

// =====================================================================
// Kernel 3: conv + silu + chunked parallel scan + b-gate.
// REVERTED to plain __launch_bounds__(800) — the (800,2) variant
// spilled (regs 52->32, L1 traffic up) and ran slower.
// =====================================================================
__global__ __launch_bounds__(800) void k_convscan(const float* __restrict__ cw,
                                                  const float* __restrict__ cb,
                                                  const float* __restrict__ al,
                                                  const float* __restrict__ be,
                                                  const float* __restrict__ ga,
                                                  const float* __restrict__ de) {
    __shared__ float ends[25][32];
    const int t = threadIdx.x;
    const int ch = t & 31, ck = t >> 5;
    const int b = blockIdx.x >> 3;
    const int ig = blockIdx.x & 7;
    const int i = ig * 32 + ch;
    const int base = b * 125 * INNER_ + i;
    const int k0 = ck * 5;

    const float* w = cw + i * 5;
    const float w0 = w[0], w1 = w[1], w2 = w[2], w3 = w[3], w4 = w[4];
    const float bias = cb[i];
    const float siga = 1.f / (1.f + __expf(-al[i]));
    const float bb = be[i], gg = ga[i], dd = de[i];

    float av[9];
#pragma unroll
    for (int q = 0; q < 9; q++) {
        int kk = k0 - 2 + q;
        av[q] = (kk >= 0 && kk <= 124) ? g_a[base + kk * INNER_] : 0.f;
    }
    float bvv[5];
#pragma unroll
    for (int q = 0; q < 5; q++) bvv[q] = g_bv[base + (k0 + q) * INNER_];

    float tv[5];
    float s = 0.f;
#pragma unroll
    for (int q = 0; q < 5; q++) {
        float acc = bias;
        acc = fmaf(w0, av[q], acc);
        acc = fmaf(w1, av[q + 1], acc);
        acc = fmaf(w2, av[q + 2], acc);
        acc = fmaf(w3, av[q + 3], acc);
        acc = fmaf(w4, av[q + 4], acc);
        float u = acc / (1.f + __expf(-acc));
        s = fmaf(siga, s, bb * u);
        tv[q] = fmaf(gg, s, dd * u);
    }
    ends[ck][ch] = s;
    __syncthreads();

    float p2 = siga * siga, p4 = p2 * p2;
    float a5 = p4 * siga;
    float st = 0.f;
    for (int jj = 0; jj < ck; jj++)
        st = fmaf(a5, st, ends[jj][ch]);
    float gc = gg * st;

    float pw = siga;
#pragma unroll
    for (int q = 0; q < 5; q++) {
        g_u[base + (k0 + q) * INNER_] = fmaf(gc, pw, tv[q]) * bvv[q];
        pw *= siga;
    }
}

// =====================================================================
// Kernel 4: out-projection — full K=256 resident; four K-quarter commit
// groups + wait-ladder. Last layer (nfw != null): final rmsnorm folded,
// writes g_fhi/g_flo directly.
// =====================================================================
__global__ __launch_bounds__(256) void k_outproj(int woff, const float* __restrict__ nfw) {
    extern __shared__ __align__(16) bf sm[];
    bf* ah = sm;             bf* al = sm + 8448;
    bf* wh = sm + 16896;     bf* wl = sm + 50688;
    const int t = threadIdx.x, lane = t & 31, w = t >> 5;
    const int mg = w >> 2, nq = w & 3;
    const int growb = blockIdx.x * 32;

    const unsigned whb = (unsigned)__cvta_generic_to_shared(wh);
    const unsigned wlb = (unsigned)__cvta_generic_to_shared(wl);

#pragma unroll
    for (int gsel = 0; gsel < 4; gsel++) {
#pragma unroll
        for (int q = 0; q < 8; q++) {
            int idx = t + 256 * q;
            int sl = idx >> 10;
            int c = idx & 1023;
            int row = c >> 3, k4 = (c & 7) + gsel * 8;
            cp16((sl ? wlb : whb) + row * 528 + k4 * 16,
                 (sl ? g_wbl : g_wbh) + woff + row * 256 + k4 * 8);
        }
        cp_commit();
    }
#pragma unroll
    for (int q = 0; q < 8; q++) {
        int idx = t + 256 * q;
        int row = idx >> 6, f4 = idx & 63;
        float4 v = *reinterpret_cast<const float4*>(&g_u[(growb + row) * INNER_ + f4 * 4]);
        bf h[4], l[4];
        split_bf(v.x, h[0], l[0]); split_bf(v.y, h[1], l[1]);
        split_bf(v.z, h[2], l[2]); split_bf(v.w, h[3], l[3]);
        *reinterpret_cast<ull*>(&ah[row * 264 + f4 * 4]) = *reinterpret_cast<ull*>(h);
        *reinterpret_cast<ull*>(&al[row * 264 + f4 * 4]) = *reinterpret_cast<ull*>(l);
    }

    float acc[4][4] = {};
#pragma unroll
    for (int qr = 0; qr < 4; qr++) {
        if (qr == 0) cp_waitg<3>();
        else if (qr == 1) cp_waitg<2>();
        else if (qr == 2) cp_waitg<1>();
        else cp_waitg<0>();
        __syncthreads();
#pragma unroll
        for (int ks2 = 0; ks2 < 4; ks2++) {
            int kst = qr * 4 + ks2;
            const int ko = kst * 16 + 2 * (lane & 3);
            const int r0 = mg * 16 + (lane >> 2);
            unsigned af[4], alf[4];
            af[0] = ldu32(&ah[r0 * 264 + ko]);       af[1] = ldu32(&ah[(r0 + 8) * 264 + ko]);
            af[2] = ldu32(&ah[r0 * 264 + ko + 8]);   af[3] = ldu32(&ah[(r0 + 8) * 264 + ko + 8]);
            alf[0] = ldu32(&al[r0 * 264 + ko]);      alf[1] = ldu32(&al[(r0 + 8) * 264 + ko]);
            alf[2] = ldu32(&al[r0 * 264 + ko + 8]);  alf[3] = ldu32(&al[(r0 + 8) * 264 + ko + 8]);
#pragma unroll
            for (int nt = 0; nt < 4; nt++) {
                int n = nq * 32 + nt * 8 + (lane >> 2);
                unsigned bh0 = ldu32(&wh[n * 264 + ko]), bh1 = ldu32(&wh[n * 264 + ko + 8]);
                unsigned bl0 = ldu32(&wl[n * 264 + ko]), bl1 = ldu32(&wl[n * 264 + ko + 8]);
                mma_bf16(acc[nt], af, bh0, bh1);
                mma_bf16(acc[nt], af, bl0, bl1);
                mma_bf16(acc[nt], alf, bh0, bh1);
            }
        }
    }
    __syncthreads();

    float (*hbuf)[132] = reinterpret_cast<float(*)[132]>(sm);
#pragma unroll
    for (int nt = 0; nt < 4; nt++) {
        int colw = nq * 32 + nt * 8 + 2 * (lane & 3);
        int r0 = mg * 16 + (lane >> 2);
        *reinterpret_cast<float2*>(&hbuf[r0][colw]) = make_float2(acc[nt][0], acc[nt][1]);
        *reinterpret_cast<float2*>(&hbuf[r0 + 8][colw]) = make_float2(acc[nt][2], acc[nt][3]);
    }
    __syncthreads();

    {
        int row = t >> 3, part = t & 7;
        int grow = growb + row;
        float ssq = 0.f;
#pragma unroll
        for (int j = 0; j < 16; j++) {
            int c = part * 16 + j;
            float nv = 2.f * g_h[grow * 128 + c] + hbuf[row][c];
            hbuf[row][c] = nv;
            ssq += nv * nv;
        }
        ssq += __shfl_xor_sync(0xffffffffu, ssq, 1);
        ssq += __shfl_xor_sync(0xffffffffu, ssq, 2);
        ssq += __shfl_xor_sync(0xffffffffu, ssq, 4);
        float sc = rsqrtf(ssq * (1.0f / 128.0f) + EPS_);
        if (part == 0) g_scale[grow] = sc;
        if (nfw == nullptr) {
#pragma unroll
            for (int j = 0; j < 16; j += 2) {
                int c = part * 16 + j;
                float v0 = hbuf[row][c], v1 = hbuf[row][c + 1];
                *reinterpret_cast<float2*>(&g_h[grow * 128 + c]) = make_float2(v0, v1);
                bf h0, l0, h1, l1;
                split_bf(v0 * sc, h0, l0); split_bf(v1 * sc, h1, l1);
                bf hp[2] = {h0, h1}, lp[2] = {l0, l1};
                *reinterpret_cast<unsigned*>(&g_nhh[grow * 128 + c]) = *reinterpret_cast<unsigned*>(hp);
                *reinterpret_cast<unsigned*>(&g_nhl[grow * 128 + c]) = *reinterpret_cast<unsigned*>(lp);
            }
        } else {
#pragma unroll
            for (int j = 0; j < 16; j += 2) {
                int c = part * 16 + j;
                float v0 = hbuf[row][c] * sc * nfw[c];
                float v1 = hbuf[row][c + 1] * sc * nfw[c + 1];
                bf h0, l0, h1, l1;
                split_bf(v0, h0, l0); split_bf(v1, h1, l1);
                bf hp[2] = {h0, h1}, lp[2] = {l0, l1};
                *reinterpret_cast<unsigned*>(&g_fhi[grow * 128 + c]) = *reinterpret_cast<unsigned*>(hp);
                *reinterpret_cast<unsigned*>(&g_flo[grow * 128 + c]) = *reinterpret_cast<unsigned*>(lp);
            }
        }
    }
}

// =====================================================================
// Kernel 5: final GEMM (bf16 hi/lo split MMA) — depth-1 register weight
// prefetch, barrier-free mainloop. Split-K 25 (640 k/block): act slabs
// 83KB dyn smem, 40 weight chunks; g_part traffic halved.
// =====================================================================
__global__ __launch_bounds__(256) void k_final(const float* __restrict__ outW) {
    extern __shared__ __align__(16) bf sm[];
    bf* fh = sm;             // 32 x 648
    bf* fl = sm + 20736;     // 32 x 648

    const int t = threadIdx.x;
    const int w = t >> 5, l = t & 31;
    const int g = l >> 2, tig = l & 3;
    const int obase = blockIdx.x * 128;
    const int ks = blockIdx.y;
    const int jbase = ks * 640;

    {
        unsigned fhb = (unsigned)__cvta_generic_to_shared(fh);
        unsigned flb = (unsigned)__cvta_generic_to_shared(fl);
#pragma unroll
        for (int q = 0; q < 10; q++) {
            int c = t + 256 * q;            // 0..2559
            int b = c / 80, kc = c - b * 80;
            cp16(fhb + b * 1296 + kc * 16, g_fhi + b * DNP_ + jbase + kc * 8);
            cp16(flb + b * 1296 + kc * 16, g_flo + b * DNP_ + jbase + kc * 8);
        }
    }
    cp_commit();

    const int n0 = obase + w * 16 + g;
    const float* w0p = outW + (size_t)n0 * DNP_ + jbase + 2 * tig;
    const float* w1p = w0p + (size_t)8 * DNP_;

    float c[2][2][4];
#pragma unroll
    for (int mt = 0; mt < 2; mt++)
#pragma unroll
        for (int nt = 0; nt < 2; nt++)
#pragma unroll
            for (int q = 0; q < 4; q++) c[mt][nt][q] = 0.f;

    float2 cur[4] = { *reinterpret_cast<const float2*>(w0p),
                      *reinterpret_cast<const float2*>(w0p + 8),
                      *reinterpret_cast<const float2*>(w1p),
                      *reinterpret_cast<const float2*>(w1p + 8) };

    cp_waitall();
    __syncthreads();

    for (int ch = 0; ch < 40; ch++) {
        int chn = (ch + 1 < 40) ? (ch + 1) : 39;
        float2 nxt[4] = { *reinterpret_cast<const float2*>(w0p + chn * 16),
                          *reinterpret_cast<const float2*>(w0p + chn * 16 + 8),
                          *reinterpret_cast<const float2*>(w1p + chn * 16),
                          *reinterpret_cast<const float2*>(w1p + chn * 16 + 8) };

        const int off = ch * 16 + 2 * tig;
        unsigned ahi[2][4], alo[2][4];
#pragma unroll
        for (int mt = 0; mt < 2; mt++) {
            int r = g + mt * 16;
            ahi[mt][0] = ldu32(&fh[r * 648 + off]);
            ahi[mt][1] = ldu32(&fh[(r + 8) * 648 + off]);
            ahi[mt][2] = ldu32(&fh[r * 648 + off + 8]);
            ahi[mt][3] = ldu32(&fh[(r + 8) * 648 + off + 8]);
            alo[mt][0] = ldu32(&fl[r * 648 + off]);
            alo[mt][1] = ldu32(&fl[(r + 8) * 648 + off]);
            alo[mt][2] = ldu32(&fl[r * 648 + off + 8]);
            alo[mt][3] = ldu32(&fl[(r + 8) * 648 + off + 8]);
        }

        unsigned bhi[2][2], blo[2][2];
#pragma unroll
        for (int nt = 0; nt < 2; nt++) {
#pragma unroll
            for (int hb = 0; hb < 2; hb++) {
                float2 wv = cur[nt * 2 + hb];
                __nv_bfloat162 h2 = __floats2bfloat162_rn(wv.x, wv.y);
                float2 lo2 = make_float2(wv.x - __bfloat162float(__low2bfloat16(h2)),
                                         wv.y - __bfloat162float(__high2bfloat16(h2)));
                __nv_bfloat162 l2 = __floats2bfloat162_rn(lo2.x, lo2.y);
                bhi[nt][hb] = *reinterpret_cast<unsigned*>(&h2);
                blo[nt][hb] = *reinterpret_cast<unsigned*>(&l2);
            }
        }

#pragma unroll
        for (int mt = 0; mt < 2; mt++)
#pragma unroll
            for (int nt = 0; nt < 2; nt++) {
                mma_bf16(c[mt][nt], ahi[mt], bhi[nt][0], bhi[nt][1]);
                mma_bf16(c[mt][nt], ahi[mt], blo[nt][0], blo[nt][1]);
                mma_bf16(c[mt][nt], alo[mt], bhi[nt][0], bhi[nt][1]);
            }

#pragma unroll
        for (int q = 0; q < 4; q++) cur[q] = nxt[q];
    }

#pragma unroll
    for (int mt = 0; mt < 2; mt++)
#pragma unroll
        for (int nt = 0; nt < 2; nt++) {
            int o = obase + w * 16 + nt * 8 + 2 * tig;
            int b0i = g + mt * 16;
            float* p0 = &g_part[(ks * B_ + b0i) * CF_ + o];
            float* p1 = &g_part[(ks * B_ + b0i + 8) * CF_ + o];
            *reinterpret_cast<float2*>(p0) = make_float2(c[mt][nt][0], c[mt][nt][1]);
            *reinterpret_cast<float2*>(p1) = make_float2(c[mt][nt][2], c[mt][nt][3]);
        }
}

// Kernel 6: reduce split-K partials + bias -> d_out (float4 vectorized)
__global__ __launch_bounds__(256) void k_reduce(const float* __restrict__ outb,
                                                float* __restrict__ out) {
    int idx = blockIdx.x * 256 + threadIdx.x;   // 49152 = 192*256 exact
    int b = idx / 1536, oq = idx - b * 1536;    // CF/4 = 1536
    float4 v = *reinterpret_cast<const float4*>(&outb[oq * 4]);
#pragma unroll
    for (int s = 0; s < KS_; s++) {
        float4 p = *reinterpret_cast<const float4*>(&g_part[(s * B_ + b) * CF_ + oq * 4]);
        v.x += p.x; v.y += p.y; v.z += p.z; v.w += p.w;
    }
    *reinterpret_cast<float4*>(&out[b * CF_ + oq * 4]) = v;
}

// =====================================================================
extern "C" void kernel_launch(void* const* d_in, const int* in_sizes, int n_in,
                              void* d_out, int out_size) {
    const float* x     = (const float*)d_in[0];
    const float* peW   = (const float*)d_in[1];
    const float* peb   = (const float*)d_in[2];
    const float* normw = (const float*)d_in[3];
    const float* ipaW  = (const float*)d_in[4];
    const float* ipbW  = (const float*)d_in[5];
    const float* convW = (const float*)d_in[6];
    const float* convb = (const float*)d_in[7];
    const float* alp   = (const float*)d_in[8];
    const float* bet   = (const float*)d_in[9];
    const float* gam   = (const float*)d_in[10];
    const float* del   = (const float*)d_in[11];
    const float* opW   = (const float*)d_in[12];
    const float* normf = (const float*)d_in[13];
    const float* outW  = (const float*)d_in[14];
    const float* outb  = (const float*)d_in[15];
    float* out = (float*)d_out;

    cudaFuncSetAttribute(k_embed,   cudaFuncAttributeMaxDynamicSharedMemorySize, SM_EMB);
    cudaFuncSetAttribute(k_inproj,  cudaFuncAttributeMaxDynamicSharedMemorySize, SM_IP);
    cudaFuncSetAttribute(k_outproj, cudaFuncAttributeMaxDynamicSharedMemorySize, SM_OP);
    cudaFuncSetAttribute(k_final,   cudaFuncAttributeMaxDynamicSharedMemorySize, SM_FIN);

    k_prep_all<<<(PREP_TOT + 255) / 256, 256>>>(peW, normw, ipaW, ipbW, opW);
    k_embed<<<M_ / 32, 256, SM_EMB>>>(x, peb);
    for (int l = 0; l < 4; l++) {
        int lb = WSZ_EMB + l * WSZ_LAYER;
        k_inproj<<<dim3(M_ / 32, 4), 256, SM_IP>>>(lb);
        k_convscan<<<B_ * 8, 800>>>(convW + l * INNER_ * 5, convb + l * INNER_,
                                    alp + l * INNER_, bet + l * INNER_,
                                    gam + l * INNER_, del + l * INNER_);
        k_outproj<<<M_ / 32, 256, SM_OP>>>(lb + 65536, (l == 3) ? normf : nullptr);
    }
    k_final<<<dim3(CF_ / 128, KS_), 256, SM_FIN>>>(outW);
    k_reduce<<<(B_ * CF_) / 1024, 256>>>(outb, out);
}

// round 15
// speedup vs baseline: 1.0679x; 1.0679x over previous
#include <cuda_runtime.h>
#include <cuda_bf16.h>
#include <math.h>

using ull = unsigned long long;
using bf = __nv_bfloat16;

constexpr int B_   = 32;
constexpr int C_   = 64;
constexpr int L_   = 512;
constexpr int NP_  = 125;
constexpr int D_   = 128;
constexpr int INNER_ = 256;
constexpr int M_   = B_ * NP_;    // 4000
constexpr int CF_  = 6144;        // C*F
constexpr int DNP_ = 16000;       // D*NP
constexpr int KS_  = 50;          // split-K for final GEMM (320 k each)
constexpr float EPS_ = 1e-5f;

// weight slab offsets (bf16 hi/lo converted once per launch)
constexpr int WOFF_EMB = 0;                 // 128 x 1024
constexpr int WSZ_EMB  = 128 * 1024;
constexpr int WSZ_LAYER = 2 * 256 * 128 + 128 * 256;  // ipa+ipb + op = 98304
constexpr int WTOT = WSZ_EMB + 4 * WSZ_LAYER;         // 524288
constexpr int PREP_TOT = WTOT + NP_ * D_;             // + PE table

// dynamic smem sizes
constexpr int SM_EMB = 25600 * 2;             // 50 KB  (double-buffered chunks)
constexpr int SM_IP  = 43520 * 2;             // 85 KB  (full K=128 resident)
constexpr int SM_OP  = 84480 * 2;             // 165 KB (full K=256 resident)

// -------- device scratch (no allocation allowed) --------
__device__ float g_h[M_ * D_];          // hidden (fp32, residual base)
__device__ float g_scale[M_];           // rmsnorm scale per row
__device__ float g_a[M_ * INNER_];      // in-proj a
__device__ float g_bv[M_ * INNER_];     // in-proj b
__device__ float g_u[M_ * INNER_];      // gated scan out
__device__ float g_part[KS_ * B_ * CF_];// split-K partials
__device__ float g_pe[NP_ * D_];        // accurate sincos PE table
__device__ bf g_fhi[B_ * DNP_];         // normalized flat, bf16 hi
__device__ bf g_flo[B_ * DNP_];         // normalized flat, bf16 lo
__device__ bf g_nhh[M_ * D_];           // normalized hidden, bf16 hi
__device__ bf g_nhl[M_ * D_];           // normalized hidden, bf16 lo
__device__ bf g_wbh[WTOT];              // weights bf16 hi
__device__ bf g_wbl[WTOT];              // weights bf16 lo

__device__ __forceinline__ void cp16(unsigned s, const void* g) {
    asm volatile("cp.async.cg.shared.global [%0],[%1],16;" :: "r"(s), "l"(g));
}
__device__ __forceinline__ void cp_commit() { asm volatile("cp.async.commit_group;"); }
__device__ __forceinline__ void cp_waitall() { asm volatile("cp.async.wait_group 0;" ::: "memory"); }
template<int N>
__device__ __forceinline__ void cp_waitg() { asm volatile("cp.async.wait_group %0;" :: "n"(N) : "memory"); }

__device__ __forceinline__ void mma_bf16(float* c, const unsigned* a,
                                         unsigned b0, unsigned b1) {
    asm volatile(
        "mma.sync.aligned.m16n8k16.row.col.f32.bf16.bf16.f32 "
        "{%0,%1,%2,%3}, {%4,%5,%6,%7}, {%8,%9}, {%0,%1,%2,%3};"
        : "+f"(c[0]), "+f"(c[1]), "+f"(c[2]), "+f"(c[3])
        : "r"(a[0]), "r"(a[1]), "r"(a[2]), "r"(a[3]), "r"(b0), "r"(b1));
}
__device__ __forceinline__ unsigned ldu32(const bf* p) {
    return *reinterpret_cast<const unsigned*>(p);
}
__device__ __forceinline__ void split_bf(float v, bf& h, bf& l) {
    h = __float2bfloat16(v);
    l = __float2bfloat16(v - __bfloat162float(h));
}

// =====================================================================
// Kernel 0: merged prep — weight slabs (bf16 hi/lo) + PE table.
// =====================================================================
__global__ __launch_bounds__(256) void k_prep_all(const float* __restrict__ peW,
                                                  const float* __restrict__ normw,
                                                  const float* __restrict__ ipaW,
                                                  const float* __restrict__ ipbW,
                                                  const float* __restrict__ opW) {
    int idx = blockIdx.x * 256 + threadIdx.x;
    if (idx >= PREP_TOT) return;
    if (idx >= WTOT) {
        int p = idx - WTOT;
        int kq = p >> 7, col = p & 127;
        int ii = col >> 1;
        float targ = (-9.210340371976184f) * (float)ii * (1.0f / 64.0f);
        float divf = (float)exp((double)targ);
        float ang = (float)kq * divf;
        double a = (double)ang;
        g_pe[p] = (float)((col & 1) ? cos(a) : sin(a));
        return;
    }
    float v;
    if (idx < WSZ_EMB) {
        v = peW[idx];
    } else {
        int r = idx - WSZ_EMB;
        int l = r / WSZ_LAYER;
        int o = r - l * WSZ_LAYER;
        if (o < 32768)       v = ipaW[l * 32768 + o] * normw[l * 128 + (o & 127)];
        else if (o < 65536)  v = ipbW[l * 32768 + (o - 32768)] * normw[l * 128 + (o & 127)];
        else                 v = opW[l * 32768 + (o - 65536)];
    }
    bf h, l2; split_bf(v, h, l2);
    g_wbh[idx] = h;
    g_wbl[idx] = l2;
}

// =====================================================================
// Kernel 1: patch-embed GEMM, double-buffered chunks (dyn smem 50KB).
// =====================================================================
__global__ __launch_bounds__(256) void k_embed(const float* __restrict__ x,
                                               const float* __restrict__ peb) {
    extern __shared__ __align__(16) bf sm[];
    const int t = threadIdx.x, lane = t & 31, w = t >> 5;
    const int mg = w >> 2, nq = w & 3;
    const int growb = blockIdx.x * 32;

    auto stage = [&](int kch, int buf) {
        bf* ah = sm + buf * 1280;
        bf* al = sm + 2560 + buf * 1280;
#pragma unroll
        for (int q = 0; q < 4; q++) {
            int idx = t + 256 * q;
            int row = idx >> 5, kk = idx & 31;
            int gk = kch * 32 + kk, c = gk >> 4, p = gk & 15;
            int grow = growb + row, bb = grow / 125, kq = grow - bb * 125;
            float v = x[(bb * C_ + c) * L_ + kq * 4 + p];
            split_bf(v, ah[row * 40 + kk], al[row * 40 + kk]);
        }
        unsigned whb = (unsigned)__cvta_generic_to_shared(sm + 5120 + buf * 5120);
        unsigned wlb = (unsigned)__cvta_generic_to_shared(sm + 15360 + buf * 5120);
#pragma unroll
        for (int q = 0; q < 2; q++) {
            int idx = t + 256 * q;
            int row = idx >> 2, k4 = idx & 3;
            cp16(whb + row * 80 + k4 * 16, g_wbh + WOFF_EMB + row * 1024 + kch * 32 + k4 * 8);
            cp16(wlb + row * 80 + k4 * 16, g_wbl + WOFF_EMB + row * 1024 + kch * 32 + k4 * 8);
        }
        cp_commit();
    };

    float acc[4][4] = {};
    stage(0, 0);

    for (int kch = 0; kch < 32; kch++) {
        const int buf = kch & 1;
        cp_waitall();
        __syncthreads();
        if (kch + 1 < 32) stage(kch + 1, buf ^ 1);

        const bf* ah = sm + buf * 1280;
        const bf* al = sm + 2560 + buf * 1280;
        const bf* wh = sm + 5120 + buf * 5120;
        const bf* wl = sm + 15360 + buf * 5120;
#pragma unroll
        for (int kst = 0; kst < 2; kst++) {
            const int ko = kst * 16 + 2 * (lane & 3);
            const int r0 = mg * 16 + (lane >> 2);
            unsigned af[4], alf[4];
            af[0] = ldu32(&ah[r0 * 40 + ko]);       af[1] = ldu32(&ah[(r0 + 8) * 40 + ko]);
            af[2] = ldu32(&ah[r0 * 40 + ko + 8]);   af[3] = ldu32(&ah[(r0 + 8) * 40 + ko + 8]);
            alf[0] = ldu32(&al[r0 * 40 + ko]);      alf[1] = ldu32(&al[(r0 + 8) * 40 + ko]);
            alf[2] = ldu32(&al[r0 * 40 + ko + 8]);  alf[3] = ldu32(&al[(r0 + 8) * 40 + ko + 8]);
#pragma unroll
            for (int nt = 0; nt < 4; nt++) {
                int n = nq * 32 + nt * 8 + (lane >> 2);
                unsigned bh0 = ldu32(&wh[n * 40 + ko]), bh1 = ldu32(&wh[n * 40 + ko + 8]);
                unsigned bl0 = ldu32(&wl[n * 40 + ko]), bl1 = ldu32(&wl[n * 40 + ko + 8]);
                mma_bf16(acc[nt], af, bh0, bh1);
                mma_bf16(acc[nt], af, bl0, bl1);
                mma_bf16(acc[nt], alf, bh0, bh1);
            }
        }
        __syncthreads();
    }

    float (*hbuf)[132] = reinterpret_cast<float(*)[132]>(sm);
#pragma unroll
    for (int nt = 0; nt < 4; nt++) {
        int colw = nq * 32 + nt * 8 + 2 * (lane & 3);
        int r0 = mg * 16 + (lane >> 2);
        *reinterpret_cast<float2*>(&hbuf[r0][colw]) = make_float2(acc[nt][0], acc[nt][1]);
        *reinterpret_cast<float2*>(&hbuf[r0 + 8][colw]) = make_float2(acc[nt][2], acc[nt][3]);
    }
    __syncthreads();

    {
        int row = t >> 3, part = t & 7;
        int grow = growb + row, bb = grow / 125, kq = grow - bb * 125;
        float ssq = 0.f;
#pragma unroll
        for (int j = 0; j < 16; j++) {
            int c = part * 16 + j;
            float v = hbuf[row][c] + peb[c] + g_pe[kq * 128 + c];
            hbuf[row][c] = v;
            ssq += v * v;
        }
        ssq += __shfl_xor_sync(0xffffffffu, ssq, 1);
        ssq += __shfl_xor_sync(0xffffffffu, ssq, 2);
        ssq += __shfl_xor_sync(0xffffffffu, ssq, 4);
        float sc = rsqrtf(ssq * (1.0f / 128.0f) + EPS_);
        if (part == 0) g_scale[grow] = sc;
#pragma unroll
        for (int j = 0; j < 16; j += 2) {
            int c = part * 16 + j;
            float v0 = hbuf[row][c], v1 = hbuf[row][c + 1];
            *reinterpret_cast<float2*>(&g_h[grow * 128 + c]) = make_float2(v0, v1);
            bf h0, l0, h1, l1;
            split_bf(v0 * sc, h0, l0); split_bf(v1 * sc, h1, l1);
            bf hp[2] = {h0, h1}, lp[2] = {l0, l1};
            *reinterpret_cast<unsigned*>(&g_nhh[grow * 128 + c]) = *reinterpret_cast<unsigned*>(hp);
            *reinterpret_cast<unsigned*>(&g_nhl[grow * 128 + c]) = *reinterpret_cast<unsigned*>(lp);
        }
    }
}

// =====================================================================
// Kernel 2: in-projections — full K=128 resident; two K-half commit
// groups + wait-ladder (fill overlaps first half's MMAs).
// =====================================================================
__global__ __launch_bounds__(256) void k_inproj(int lbase) {
    extern __shared__ __align__(16) bf sm[];
    bf* ah = sm;            bf* al = sm + 4352;
    bf* wh = sm + 8704;     bf* wl = sm + 26112;
    const int t = threadIdx.x, lane = t & 31, w = t >> 5;
    const int mg = w >> 2, nq = w & 3;
    const int growb = blockIdx.x * 32;
    const int ny = blockIdx.y;
    const int woff = lbase + ny * 128 * 128;

    const unsigned ahb = (unsigned)__cvta_generic_to_shared(ah);
    const unsigned alb = (unsigned)__cvta_generic_to_shared(al);
    const unsigned whb = (unsigned)__cvta_generic_to_shared(wh);
    const unsigned wlb = (unsigned)__cvta_generic_to_shared(wl);

#pragma unroll
    for (int gsel = 0; gsel < 2; gsel++) {
#pragma unroll
        for (int q = 0; q < 2; q++) {
            int idx = t + 256 * q;
            int sl = idx >> 8;
            int c = idx & 255;
            int row = c >> 3, k4 = (c & 7) + gsel * 8;
            cp16((sl ? alb : ahb) + row * 272 + k4 * 16,
                 (sl ? g_nhl : g_nhh) + (growb + row) * 128 + k4 * 8);
        }
#pragma unroll
        for (int q = 0; q < 8; q++) {
            int idx = t + 256 * q;
            int sl = idx >> 10;
            int c = idx & 1023;
            int row = c >> 3, k4 = (c & 7) + gsel * 8;
            cp16((sl ? wlb : whb) + row * 272 + k4 * 16,
                 (sl ? g_wbl : g_wbh) + woff + row * 128 + k4 * 8);
        }
        cp_commit();
    }

    float acc[4][4] = {};
#pragma unroll
    for (int half = 0; half < 2; half++) {
        if (half == 0) cp_waitg<1>(); else cp_waitg<0>();
        __syncthreads();
#pragma unroll
        for (int ks2 = 0; ks2 < 4; ks2++) {
            int kst = half * 4 + ks2;
            const int ko = kst * 16 + 2 * (lane & 3);
            const int r0 = mg * 16 + (lane >> 2);
            unsigned af[4], alf[4];
            af[0] = ldu32(&ah[r0 * 136 + ko]);       af[1] = ldu32(&ah[(r0 + 8) * 136 + ko]);
            af[2] = ldu32(&ah[r0 * 136 + ko + 8]);   af[3] = ldu32(&ah[(r0 + 8) * 136 + ko + 8]);
            alf[0] = ldu32(&al[r0 * 136 + ko]);      alf[1] = ldu32(&al[(r0 + 8) * 136 + ko]);
            alf[2] = ldu32(&al[r0 * 136 + ko + 8]);  alf[3] = ldu32(&al[(r0 + 8) * 136 + ko + 8]);
#pragma unroll
            for (int nt = 0; nt < 4; nt++) {
                int n = nq * 32 + nt * 8 + (lane >> 2);
                unsigned bh0 = ldu32(&wh[n * 136 + ko]), bh1 = ldu32(&wh[n * 136 + ko + 8]);
                unsigned bl0 = ldu32(&wl[n * 136 + ko]), bl1 = ldu32(&wl[n * 136 + ko + 8]);
                mma_bf16(acc[nt], af, bh0, bh1);
                mma_bf16(acc[nt], af, bl0, bl1);
                mma_bf16(acc[nt], alf, bh0, bh1);
            }
        }
    }

    float* out = (ny < 2) ? g_a : g_bv;
    const int colb = (ny & 1) * 128;
#pragma unroll
    for (int nt = 0; nt < 4; nt++) {
        int col = colb + nq * 32 + nt * 8 + 2 * (lane & 3);
        int r0 = growb + mg * 16 + (lane >> 2);
        *reinterpret_cast<float2*>(&out[r0 * INNER_ + col]) = make_float2(acc[nt][0], acc[nt][1]);
        *reinterpret_cast<float2*>(&out[(r0 + 8) * INNER_ + col]) = make_float2(acc[nt][2], acc[nt][3]);
    }
}

// =====================================================================
// Kernel 3: conv + silu + chunked parallel scan + b-gate.
// 400-thread blocks (16 channels x 25 chunks): at regs=52 the 64K reg
// file fits THREE 400-thr blocks (58% occ) vs one 800-thr block (39%).
// Grid: 32 b x 16 channel-groups = 512 blocks.
// =====================================================================
__global__ __launch_bounds__(400) void k_convscan(const float* __restrict__ cw,
                                                  const float* __restrict__ cb,
                                                  const float* __restrict__ al,
                                                  const float* __restrict__ be,
                                                  const float* __restrict__ ga,
                                                  const float* __restrict__ de) {
    __shared__ float ends[25][16];
    const int t = threadIdx.x;
    const int ch = t & 15, ck = t >> 4;          // 16 channels, 25 chunks
    const int b = blockIdx.x >> 4;
    const int ig = blockIdx.x & 15;
    const int i = ig * 16 + ch;
    const int base = b * 125 * INNER_ + i;
    const int k0 = ck * 5;

    const float* w = cw + i * 5;
    const float w0 = w[0], w1 = w[1], w2 = w[2], w3 = w[3], w4 = w[4];
    const float bias = cb[i];
    const float siga = 1.f / (1.f + __expf(-al[i]));
    const float bb = be[i], gg = ga[i], dd = de[i];

    float av[9];
#pragma unroll
    for (int q = 0; q < 9; q++) {
        int kk = k0 - 2 + q;
        av[q] = (kk >= 0 && kk <= 124) ? g_a[base + kk * INNER_] : 0.f;
    }
    float bvv[5];
#pragma unroll
    for (int q = 0; q < 5; q++) bvv[q] = g_bv[base + (k0 + q) * INNER_];

    float tv[5];
    float s = 0.f;
#pragma unroll
    for (int q = 0; q < 5; q++) {
        float acc = bias;
        acc = fmaf(w0, av[q], acc);
        acc = fmaf(w1, av[q + 1], acc);
        acc = fmaf(w2, av[q + 2], acc);
        acc = fmaf(w3, av[q + 3], acc);
        acc = fmaf(w4, av[q + 4], acc);
        float u = acc / (1.f + __expf(-acc));
        s = fmaf(siga, s, bb * u);
        tv[q] = fmaf(gg, s, dd * u);
    }
    ends[ck][ch] = s;
    __syncthreads();

    float p2 = siga * siga, p4 = p2 * p2;
    float a5 = p4 * siga;
    float st = 0.f;
    for (int jj = 0; jj < ck; jj++)
        st = fmaf(a5, st, ends[jj][ch]);
    float gc = gg * st;

    float pw = siga;
#pragma unroll
    for (int q = 0; q < 5; q++) {
        g_u[base + (k0 + q) * INNER_] = fmaf(gc, pw, tv[q]) * bvv[q];
        pw *= siga;
    }
}

// =====================================================================
// Kernel 4: out-projection — full K=256 resident; four K-quarter commit
// groups + wait-ladder. Last layer (nfw != null): final rmsnorm folded,
// writes g_fhi/g_flo directly.
// =====================================================================
__global__ __launch_bounds__(256) void k_outproj(int woff, const float* __restrict__ nfw) {
    extern __shared__ __align__(16) bf sm[];
    bf* ah = sm;             bf* al = sm + 8448;
    bf* wh = sm + 16896;     bf* wl = sm + 50688;
    const int t = threadIdx.x, lane = t & 31, w = t >> 5;
    const int mg = w >> 2, nq = w & 3;
    const int growb = blockIdx.x * 32;

    const unsigned whb = (unsigned)__cvta_generic_to_shared(wh);
    const unsigned wlb = (unsigned)__cvta_generic_to_shared(wl);

#pragma unroll
    for (int gsel = 0; gsel < 4; gsel++) {
#pragma unroll
        for (int q = 0; q < 8; q++) {
            int idx = t + 256 * q;
            int sl = idx >> 10;
            int c = idx & 1023;
            int row = c >> 3, k4 = (c & 7) + gsel * 8;
            cp16((sl ? wlb : whb) + row * 528 + k4 * 16,
                 (sl ? g_wbl : g_wbh) + woff + row * 256 + k4 * 8);
        }
        cp_commit();
    }
#pragma unroll
    for (int q = 0; q < 8; q++) {
        int idx = t + 256 * q;
        int row = idx >> 6, f4 = idx & 63;
        float4 v = *reinterpret_cast<const float4*>(&g_u[(growb + row) * INNER_ + f4 * 4]);
        bf h[4], l[4];
        split_bf(v.x, h[0], l[0]); split_bf(v.y, h[1], l[1]);
        split_bf(v.z, h[2], l[2]); split_bf(v.w, h[3], l[3]);
        *reinterpret_cast<ull*>(&ah[row * 264 + f4 * 4]) = *reinterpret_cast<ull*>(h);
        *reinterpret_cast<ull*>(&al[row * 264 + f4 * 4]) = *reinterpret_cast<ull*>(l);
    }

    float acc[4][4] = {};
#pragma unroll
    for (int qr = 0; qr < 4; qr++) {
        if (qr == 0) cp_waitg<3>();
        else if (qr == 1) cp_waitg<2>();
        else if (qr == 2) cp_waitg<1>();
        else cp_waitg<0>();
        __syncthreads();
#pragma unroll
        for (int ks2 = 0; ks2 < 4; ks2++) {
            int kst = qr * 4 + ks2;
            const int ko = kst * 16 + 2 * (lane & 3);
            const int r0 = mg * 16 + (lane >> 2);
            unsigned af[4], alf[4];
            af[0] = ldu32(&ah[r0 * 264 + ko]);       af[1] = ldu32(&ah[(r0 + 8) * 264 + ko]);
            af[2] = ldu32(&ah[r0 * 264 + ko + 8]);   af[3] = ldu32(&ah[(r0 + 8) * 264 + ko + 8]);
            alf[0] = ldu32(&al[r0 * 264 + ko]);      alf[1] = ldu32(&al[(r0 + 8) * 264 + ko]);
            alf[2] = ldu32(&al[r0 * 264 + ko + 8]);  alf[3] = ldu32(&al[(r0 + 8) * 264 + ko + 8]);
#pragma unroll
            for (int nt = 0; nt < 4; nt++) {
                int n = nq * 32 + nt * 8 + (lane >> 2);
                unsigned bh0 = ldu32(&wh[n * 264 + ko]), bh1 = ldu32(&wh[n * 264 + ko + 8]);
                unsigned bl0 = ldu32(&wl[n * 264 + ko]), bl1 = ldu32(&wl[n * 264 + ko + 8]);
                mma_bf16(acc[nt], af, bh0, bh1);
                mma_bf16(acc[nt], af, bl0, bl1);
                mma_bf16(acc[nt], alf, bh0, bh1);
            }
        }
    }
    __syncthreads();

    float (*hbuf)[132] = reinterpret_cast<float(*)[132]>(sm);
#pragma unroll
    for (int nt = 0; nt < 4; nt++) {
        int colw = nq * 32 + nt * 8 + 2 * (lane & 3);
        int r0 = mg * 16 + (lane >> 2);
        *reinterpret_cast<float2*>(&hbuf[r0][colw]) = make_float2(acc[nt][0], acc[nt][1]);
        *reinterpret_cast<float2*>(&hbuf[r0 + 8][colw]) = make_float2(acc[nt][2], acc[nt][3]);
    }
    __syncthreads();

    {
        int row = t >> 3, part = t & 7;
        int grow = growb + row;
        float ssq = 0.f;
#pragma unroll
        for (int j = 0; j < 16; j++) {
            int c = part * 16 + j;
            float nv = 2.f * g_h[grow * 128 + c] + hbuf[row][c];
            hbuf[row][c] = nv;
            ssq += nv * nv;
        }
        ssq += __shfl_xor_sync(0xffffffffu, ssq, 1);
        ssq += __shfl_xor_sync(0xffffffffu, ssq, 2);
        ssq += __shfl_xor_sync(0xffffffffu, ssq, 4);
        float sc = rsqrtf(ssq * (1.0f / 128.0f) + EPS_);
        if (part == 0) g_scale[grow] = sc;
        if (nfw == nullptr) {
#pragma unroll
            for (int j = 0; j < 16; j += 2) {
                int c = part * 16 + j;
                float v0 = hbuf[row][c], v1 = hbuf[row][c + 1];
                *reinterpret_cast<float2*>(&g_h[grow * 128 + c]) = make_float2(v0, v1);
                bf h0, l0, h1, l1;
                split_bf(v0 * sc, h0, l0); split_bf(v1 * sc, h1, l1);
                bf hp[2] = {h0, h1}, lp[2] = {l0, l1};
                *reinterpret_cast<unsigned*>(&g_nhh[grow * 128 + c]) = *reinterpret_cast<unsigned*>(hp);
                *reinterpret_cast<unsigned*>(&g_nhl[grow * 128 + c]) = *reinterpret_cast<unsigned*>(lp);
            }
        } else {
#pragma unroll
            for (int j = 0; j < 16; j += 2) {
                int c = part * 16 + j;
                float v0 = hbuf[row][c] * sc * nfw[c];
                float v1 = hbuf[row][c + 1] * sc * nfw[c + 1];
                bf h0, l0, h1, l1;
                split_bf(v0, h0, l0); split_bf(v1, h1, l1);
                bf hp[2] = {h0, h1}, lp[2] = {l0, l1};
                *reinterpret_cast<unsigned*>(&g_fhi[grow * 128 + c]) = *reinterpret_cast<unsigned*>(hp);
                *reinterpret_cast<unsigned*>(&g_flo[grow * 128 + c]) = *reinterpret_cast<unsigned*>(lp);
            }
        }
    }
}

// =====================================================================
// Kernel 5: final GEMM (bf16 hi/lo split MMA) — FROZEN R12 version:
// KS=50, static 41KB smem (~5 blocks/SM), depth-1 register weight
// prefetch, barrier-free mainloop. Occupancy carries this kernel; do
// not trade it away (R9/R11/R14 all lost doing so).
// =====================================================================
__global__ __launch_bounds__(256) void k_final(const float* __restrict__ outW) {
    __shared__ __align__(16) bf fh[32][328];
    __shared__ __align__(16) bf fl[32][328];

    const int t = threadIdx.x;
    const int w = t >> 5, l = t & 31;
    const int g = l >> 2, tig = l & 3;
    const int obase = blockIdx.x * 128;
    const int ks = blockIdx.y;
    const int jbase = ks * 320;

    {
        unsigned fhb = (unsigned)__cvta_generic_to_shared(&fh[0][0]);
        unsigned flb = (unsigned)__cvta_generic_to_shared(&fl[0][0]);
#pragma unroll
        for (int q = 0; q < 5; q++) {
            int c = t + 256 * q;
            int b = c / 40, kc = c - b * 40;
            cp16(fhb + b * 656 + kc * 16, g_fhi + b * DNP_ + jbase + kc * 8);
            cp16(flb + b * 656 + kc * 16, g_flo + b * DNP_ + jbase + kc * 8);
        }
    }
    cp_commit();

    const int n0 = obase + w * 16 + g;
    const float* w0p = outW + (size_t)n0 * DNP_ + jbase + 2 * tig;
    const float* w1p = w0p + (size_t)8 * DNP_;

    float c[2][2][4];
#pragma unroll
    for (int mt = 0; mt < 2; mt++)
#pragma unroll
        for (int nt = 0; nt < 2; nt++)
#pragma unroll
            for (int q = 0; q < 4; q++) c[mt][nt][q] = 0.f;

    float2 cur[4] = { *reinterpret_cast<const float2*>(w0p),
                      *reinterpret_cast<const float2*>(w0p + 8),
                      *reinterpret_cast<const float2*>(w1p),
                      *reinterpret_cast<const float2*>(w1p + 8) };

    cp_waitall();
    __syncthreads();

    for (int ch = 0; ch < 20; ch++) {
        int chn = (ch + 1 < 20) ? (ch + 1) : 19;
        float2 nxt[4] = { *reinterpret_cast<const float2*>(w0p + chn * 16),
                          *reinterpret_cast<const float2*>(w0p + chn * 16 + 8),
                          *reinterpret_cast<const float2*>(w1p + chn * 16),
                          *reinterpret_cast<const float2*>(w1p + chn * 16 + 8) };

        const int off = ch * 16 + 2 * tig;
        unsigned ahi[2][4], alo[2][4];
#pragma unroll
        for (int mt = 0; mt < 2; mt++) {
            int r = g + mt * 16;
            ahi[mt][0] = ldu32(&fh[r][off]);
            ahi[mt][1] = ldu32(&fh[r + 8][off]);
            ahi[mt][2] = ldu32(&fh[r][off + 8]);
            ahi[mt][3] = ldu32(&fh[r + 8][off + 8]);
            alo[mt][0] = ldu32(&fl[r][off]);
            alo[mt][1] = ldu32(&fl[r + 8][off]);
            alo[mt][2] = ldu32(&fl[r][off + 8]);
            alo[mt][3] = ldu32(&fl[r + 8][off + 8]);
        }

        unsigned bhi[2][2], blo[2][2];
#pragma unroll
        for (int nt = 0; nt < 2; nt++) {
#pragma unroll
            for (int hb = 0; hb < 2; hb++) {
                float2 wv = cur[nt * 2 + hb];
                __nv_bfloat162 h2 = __floats2bfloat162_rn(wv.x, wv.y);
                float2 lo2 = make_float2(wv.x - __bfloat162float(__low2bfloat16(h2)),
                                         wv.y - __bfloat162float(__high2bfloat16(h2)));
                __nv_bfloat162 l2 = __floats2bfloat162_rn(lo2.x, lo2.y);
                bhi[nt][hb] = *reinterpret_cast<unsigned*>(&h2);
                blo[nt][hb] = *reinterpret_cast<unsigned*>(&l2);
            }
        }

#pragma unroll
        for (int mt = 0; mt < 2; mt++)
#pragma unroll
            for (int nt = 0; nt < 2; nt++) {
                mma_bf16(c[mt][nt], ahi[mt], bhi[nt][0], bhi[nt][1]);
                mma_bf16(c[mt][nt], ahi[mt], blo[nt][0], blo[nt][1]);
                mma_bf16(c[mt][nt], alo[mt], bhi[nt][0], bhi[nt][1]);
            }

#pragma unroll
        for (int q = 0; q < 4; q++) cur[q] = nxt[q];
    }

#pragma unroll
    for (int mt = 0; mt < 2; mt++)
#pragma unroll
        for (int nt = 0; nt < 2; nt++) {
            int o = obase + w * 16 + nt * 8 + 2 * tig;
            int b0i = g + mt * 16;
            float* p0 = &g_part[(ks * B_ + b0i) * CF_ + o];
            float* p1 = &g_part[(ks * B_ + b0i + 8) * CF_ + o];
            *reinterpret_cast<float2*>(p0) = make_float2(c[mt][nt][0], c[mt][nt][1]);
            *reinterpret_cast<float2*>(p1) = make_float2(c[mt][nt][2], c[mt][nt][3]);
        }
}

// Kernel 6: reduce split-K partials + bias -> d_out (float4 vectorized)
__global__ __launch_bounds__(256) void k_reduce(const float* __restrict__ outb,
                                                float* __restrict__ out) {
    int idx = blockIdx.x * 256 + threadIdx.x;   // 49152 = 192*256 exact
    int b = idx / 1536, oq = idx - b * 1536;    // CF/4 = 1536
    float4 v = *reinterpret_cast<const float4*>(&outb[oq * 4]);
#pragma unroll
    for (int s = 0; s < KS_; s++) {
        float4 p = *reinterpret_cast<const float4*>(&g_part[(s * B_ + b) * CF_ + oq * 4]);
        v.x += p.x; v.y += p.y; v.z += p.z; v.w += p.w;
    }
    *reinterpret_cast<float4*>(&out[b * CF_ + oq * 4]) = v;
}

// =====================================================================
extern "C" void kernel_launch(void* const* d_in, const int* in_sizes, int n_in,
                              void* d_out, int out_size) {
    const float* x     = (const float*)d_in[0];
    const float* peW   = (const float*)d_in[1];
    const float* peb   = (const float*)d_in[2];
    const float* normw = (const float*)d_in[3];
    const float* ipaW  = (const float*)d_in[4];
    const float* ipbW  = (const float*)d_in[5];
    const float* convW = (const float*)d_in[6];
    const float* convb = (const float*)d_in[7];
    const float* alp   = (const float*)d_in[8];
    const float* bet   = (const float*)d_in[9];
    const float* gam   = (const float*)d_in[10];
    const float* del   = (const float*)d_in[11];
    const float* opW   = (const float*)d_in[12];
    const float* normf = (const float*)d_in[13];
    const float* outW  = (const float*)d_in[14];
    const float* outb  = (const float*)d_in[15];
    float* out = (float*)d_out;

    cudaFuncSetAttribute(k_embed,   cudaFuncAttributeMaxDynamicSharedMemorySize, SM_EMB);
    cudaFuncSetAttribute(k_inproj,  cudaFuncAttributeMaxDynamicSharedMemorySize, SM_IP);
    cudaFuncSetAttribute(k_outproj, cudaFuncAttributeMaxDynamicSharedMemorySize, SM_OP);

    k_prep_all<<<(PREP_TOT + 255) / 256, 256>>>(peW, normw, ipaW, ipbW, opW);
    k_embed<<<M_ / 32, 256, SM_EMB>>>(x, peb);
    for (int l = 0; l < 4; l++) {
        int lb = WSZ_EMB + l * WSZ_LAYER;
        k_inproj<<<dim3(M_ / 32, 4), 256, SM_IP>>>(lb);
        k_convscan<<<B_ * 16, 400>>>(convW + l * INNER_ * 5, convb + l * INNER_,
                                     alp + l * INNER_, bet + l * INNER_,
                                     gam + l * INNER_, del + l * INNER_);
        k_outproj<<<M_ / 32, 256, SM_OP>>>(lb + 65536, (l == 3) ? normf : nullptr);
    }
    k_final<<<dim3(CF_ / 128, KS_), 256>>>(outW);
    k_reduce<<<(B_ * CF_) / 1024, 256>>>(outb, out);
}

// round 16
// speedup vs baseline: 1.1071x; 1.0367x over previous
#include <cuda_runtime.h>
#include <cuda_bf16.h>
#include <math.h>

using ull = unsigned long long;
using bf = __nv_bfloat16;

constexpr int B_   = 32;
constexpr int C_   = 64;
constexpr int L_   = 512;
constexpr int NP_  = 125;
constexpr int D_   = 128;
constexpr int INNER_ = 256;
constexpr int M_   = B_ * NP_;    // 4000
constexpr int CF_  = 6144;        // C*F
constexpr int DNP_ = 16000;       // D*NP
constexpr int KS_  = 50;          // split-K for final GEMM (320 k each)
constexpr float EPS_ = 1e-5f;

// weight slab offsets (bf16 hi/lo converted once per launch)
constexpr int WOFF_EMB = 0;                 // 128 x 1024
constexpr int WSZ_EMB  = 128 * 1024;
constexpr int WSZ_LAYER = 2 * 256 * 128 + 128 * 256;  // ipa+ipb + op = 98304
constexpr int WTOT = WSZ_EMB + 4 * WSZ_LAYER;         // 524288
constexpr int PREP_TOT = WTOT + NP_ * D_;             // + PE table

// dynamic smem sizes
constexpr int SM_EMB = 25600 * 2;             // 50 KB  (double-buffered chunks)
constexpr int SM_IP  = 43520 * 2;             // 85 KB  (full K=128 resident)
constexpr int SM_OP  = 84480 * 2;             // 165 KB (full K=256 resident)

// -------- device scratch (no allocation allowed) --------
__device__ float g_h[M_ * D_];          // hidden (fp32, residual base)
__device__ float g_scale[M_];           // rmsnorm scale per row
__device__ float g_a[M_ * INNER_];      // in-proj a
__device__ float g_bv[M_ * INNER_];     // in-proj b
__device__ float g_u[M_ * INNER_];      // gated scan out
__device__ float g_part[KS_ * B_ * CF_];// split-K partials
__device__ float g_pe[NP_ * D_];        // accurate sincos PE table
__device__ bf g_fhi[B_ * DNP_];         // normalized flat, bf16 hi
__device__ bf g_flo[B_ * DNP_];         // normalized flat, bf16 lo
__device__ bf g_nhh[M_ * D_];           // normalized hidden, bf16 hi
__device__ bf g_nhl[M_ * D_];           // normalized hidden, bf16 lo
__device__ bf g_wbh[WTOT];              // weights bf16 hi
__device__ bf g_wbl[WTOT];              // weights bf16 lo

__device__ __forceinline__ void cp16(unsigned s, const void* g) {
    asm volatile("cp.async.cg.shared.global [%0],[%1],16;" :: "r"(s), "l"(g));
}
__device__ __forceinline__ void cp_commit() { asm volatile("cp.async.commit_group;"); }
__device__ __forceinline__ void cp_waitall() { asm volatile("cp.async.wait_group 0;" ::: "memory"); }
template<int N>
__device__ __forceinline__ void cp_waitg() { asm volatile("cp.async.wait_group %0;" :: "n"(N) : "memory"); }

__device__ __forceinline__ void mma_bf16(float* c, const unsigned* a,
                                         unsigned b0, unsigned b1) {
    asm volatile(
        "mma.sync.aligned.m16n8k16.row.col.f32.bf16.bf16.f32 "
        "{%0,%1,%2,%3}, {%4,%5,%6,%7}, {%8,%9}, {%0,%1,%2,%3};"
        : "+f"(c[0]), "+f"(c[1]), "+f"(c[2]), "+f"(c[3])
        : "r"(a[0]), "r"(a[1]), "r"(a[2]), "r"(a[3]), "r"(b0), "r"(b1));
}
__device__ __forceinline__ unsigned ldu32(const bf* p) {
    return *reinterpret_cast<const unsigned*>(p);
}
__device__ __forceinline__ void split_bf(float v, bf& h, bf& l) {
    h = __float2bfloat16(v);
    l = __float2bfloat16(v - __bfloat162float(h));
}

// =====================================================================
// Kernel 0: merged prep — weight slabs (bf16 hi/lo) + PE table.
// =====================================================================
__global__ __launch_bounds__(256) void k_prep_all(const float* __restrict__ peW,
                                                  const float* __restrict__ normw,
                                                  const float* __restrict__ ipaW,
                                                  const float* __restrict__ ipbW,
                                                  const float* __restrict__ opW) {
    int idx = blockIdx.x * 256 + threadIdx.x;
    if (idx >= PREP_TOT) return;
    if (idx >= WTOT) {
        int p = idx - WTOT;
        int kq = p >> 7, col = p & 127;
        int ii = col >> 1;
        float targ = (-9.210340371976184f) * (float)ii * (1.0f / 64.0f);
        float divf = (float)exp((double)targ);
        float ang = (float)kq * divf;
        double a = (double)ang;
        g_pe[p] = (float)((col & 1) ? cos(a) : sin(a));
        return;
    }
    float v;
    if (idx < WSZ_EMB) {
        v = peW[idx];
    } else {
        int r = idx - WSZ_EMB;
        int l = r / WSZ_LAYER;
        int o = r - l * WSZ_LAYER;
        if (o < 32768)       v = ipaW[l * 32768 + o] * normw[l * 128 + (o & 127)];
        else if (o < 65536)  v = ipbW[l * 32768 + (o - 32768)] * normw[l * 128 + (o & 127)];
        else                 v = opW[l * 32768 + (o - 65536)];
    }
    bf h, l2; split_bf(v, h, l2);
    g_wbh[idx] = h;
    g_wbl[idx] = l2;
}

// =====================================================================
// Kernel 1: patch-embed GEMM, double-buffered chunks (dyn smem 50KB).
// =====================================================================
__global__ __launch_bounds__(256) void k_embed(const float* __restrict__ x,
                                               const float* __restrict__ peb) {
    extern __shared__ __align__(16) bf sm[];
    const int t = threadIdx.x, lane = t & 31, w = t >> 5;
    const int mg = w >> 2, nq = w & 3;
    const int growb = blockIdx.x * 32;

    auto stage = [&](int kch, int buf) {
        bf* ah = sm + buf * 1280;
        bf* al = sm + 2560 + buf * 1280;
#pragma unroll
        for (int q = 0; q < 4; q++) {
            int idx = t + 256 * q;
            int row = idx >> 5, kk = idx & 31;
            int gk = kch * 32 + kk, c = gk >> 4, p = gk & 15;
            int grow = growb + row, bb = grow / 125, kq = grow - bb * 125;
            float v = x[(bb * C_ + c) * L_ + kq * 4 + p];
            split_bf(v, ah[row * 40 + kk], al[row * 40 + kk]);
        }
        unsigned whb = (unsigned)__cvta_generic_to_shared(sm + 5120 + buf * 5120);
        unsigned wlb = (unsigned)__cvta_generic_to_shared(sm + 15360 + buf * 5120);
#pragma unroll
        for (int q = 0; q < 2; q++) {
            int idx = t + 256 * q;
            int row = idx >> 2, k4 = idx & 3;
            cp16(whb + row * 80 + k4 * 16, g_wbh + WOFF_EMB + row * 1024 + kch * 32 + k4 * 8);
            cp16(wlb + row * 80 + k4 * 16, g_wbl + WOFF_EMB + row * 1024 + kch * 32 + k4 * 8);
        }
        cp_commit();
    };

    float acc[4][4] = {};
    stage(0, 0);

    for (int kch = 0; kch < 32; kch++) {
        const int buf = kch & 1;
        cp_waitall();
        __syncthreads();
        if (kch + 1 < 32) stage(kch + 1, buf ^ 1);

        const bf* ah = sm + buf * 1280;
        const bf* al = sm + 2560 + buf * 1280;
        const bf* wh = sm + 5120 + buf * 5120;
        const bf* wl = sm + 15360 + buf * 5120;
#pragma unroll
        for (int kst = 0; kst < 2; kst++) {
            const int ko = kst * 16 + 2 * (lane & 3);
            const int r0 = mg * 16 + (lane >> 2);
            unsigned af[4], alf[4];
            af[0] = ldu32(&ah[r0 * 40 + ko]);       af[1] = ldu32(&ah[(r0 + 8) * 40 + ko]);
            af[2] = ldu32(&ah[r0 * 40 + ko + 8]);   af[3] = ldu32(&ah[(r0 + 8) * 40 + ko + 8]);
            alf[0] = ldu32(&al[r0 * 40 + ko]);      alf[1] = ldu32(&al[(r0 + 8) * 40 + ko]);
            alf[2] = ldu32(&al[r0 * 40 + ko + 8]);  alf[3] = ldu32(&al[(r0 + 8) * 40 + ko + 8]);
#pragma unroll
            for (int nt = 0; nt < 4; nt++) {
                int n = nq * 32 + nt * 8 + (lane >> 2);
                unsigned bh0 = ldu32(&wh[n * 40 + ko]), bh1 = ldu32(&wh[n * 40 + ko + 8]);
                unsigned bl0 = ldu32(&wl[n * 40 + ko]), bl1 = ldu32(&wl[n * 40 + ko + 8]);
                mma_bf16(acc[nt], af, bh0, bh1);
                mma_bf16(acc[nt], af, bl0, bl1);
                mma_bf16(acc[nt], alf, bh0, bh1);
            }
        }
        __syncthreads();
    }

    float (*hbuf)[132] = reinterpret_cast<float(*)[132]>(sm);
#pragma unroll
    for (int nt = 0; nt < 4; nt++) {
        int colw = nq * 32 + nt * 8 + 2 * (lane & 3);
        int r0 = mg * 16 + (lane >> 2);
        *reinterpret_cast<float2*>(&hbuf[r0][colw]) = make_float2(acc[nt][0], acc[nt][1]);
        *reinterpret_cast<float2*>(&hbuf[r0 + 8][colw]) = make_float2(acc[nt][2], acc[nt][3]);
    }
    __syncthreads();

    {
        int row = t >> 3, part = t & 7;
        int grow = growb + row, bb = grow / 125, kq = grow - bb * 125;
        float ssq = 0.f;
#pragma unroll
        for (int j = 0; j < 16; j++) {
            int c = part * 16 + j;
            float v = hbuf[row][c] + peb[c] + g_pe[kq * 128 + c];
            hbuf[row][c] = v;
            ssq += v * v;
        }
        ssq += __shfl_xor_sync(0xffffffffu, ssq, 1);
        ssq += __shfl_xor_sync(0xffffffffu, ssq, 2);
        ssq += __shfl_xor_sync(0xffffffffu, ssq, 4);
        float sc = rsqrtf(ssq * (1.0f / 128.0f) + EPS_);
        if (part == 0) g_scale[grow] = sc;
#pragma unroll
        for (int j = 0; j < 16; j += 2) {
            int c = part * 16 + j;
            float v0 = hbuf[row][c], v1 = hbuf[row][c + 1];
            *reinterpret_cast<float2*>(&g_h[grow * 128 + c]) = make_float2(v0, v1);
            bf h0, l0, h1, l1;
            split_bf(v0 * sc, h0, l0); split_bf(v1 * sc, h1, l1);
            bf hp[2] = {h0, h1}, lp[2] = {l0, l1};
            *reinterpret_cast<unsigned*>(&g_nhh[grow * 128 + c]) = *reinterpret_cast<unsigned*>(hp);
            *reinterpret_cast<unsigned*>(&g_nhl[grow * 128 + c]) = *reinterpret_cast<unsigned*>(lp);
        }
    }
}

// =====================================================================
// Kernel 2: in-projections — full K=128 resident; two K-half commit
// groups + wait-ladder (fill overlaps first half's MMAs).
// =====================================================================
__global__ __launch_bounds__(256) void k_inproj(int lbase) {
    extern __shared__ __align__(16) bf sm[];
    bf* ah = sm;            bf* al = sm + 4352;
    bf* wh = sm + 8704;     bf* wl = sm + 26112;
    const int t = threadIdx.x, lane = t & 31, w = t >> 5;
    const int mg = w >> 2, nq = w & 3;
    const int growb = blockIdx.x * 32;
    const int ny = blockIdx.y;
    const int woff = lbase + ny * 128 * 128;

    const unsigned ahb = (unsigned)__cvta_generic_to_shared(ah);
    const unsigned alb = (unsigned)__cvta_generic_to_shared(al);
    const unsigned whb = (unsigned)__cvta_generic_to_shared(wh);
    const unsigned wlb = (unsigned)__cvta_generic_to_shared(wl);

#pragma unroll
    for (int gsel = 0; gsel < 2; gsel++) {
#pragma unroll
        for (int q = 0; q < 2; q++) {
            int idx = t + 256 * q;
            int sl = idx >> 8;
            int c = idx & 255;
            int row = c >> 3, k4 = (c & 7) + gsel * 8;
            cp16((sl ? alb : ahb) + row * 272 + k4 * 16,
                 (sl ? g_nhl : g_nhh) + (growb + row) * 128 + k4 * 8);
        }
#pragma unroll
        for (int q = 0; q < 8; q++) {
            int idx = t + 256 * q;
            int sl = idx >> 10;
            int c = idx & 1023;
            int row = c >> 3, k4 = (c & 7) + gsel * 8;
            cp16((sl ? wlb : whb) + row * 272 + k4 * 16,
                 (sl ? g_wbl : g_wbh) + woff + row * 128 + k4 * 8);
        }
        cp_commit();
    }

    float acc[4][4] = {};
#pragma unroll
    for (int half = 0; half < 2; half++) {
        if (half == 0) cp_waitg<1>(); else cp_waitg<0>();
        __syncthreads();
#pragma unroll
        for (int ks2 = 0; ks2 < 4; ks2++) {
            int kst = half * 4 + ks2;
            const int ko = kst * 16 + 2 * (lane & 3);
            const int r0 = mg * 16 + (lane >> 2);
            unsigned af[4], alf[4];
            af[0] = ldu32(&ah[r0 * 136 + ko]);       af[1] = ldu32(&ah[(r0 + 8) * 136 + ko]);
            af[2] = ldu32(&ah[r0 * 136 + ko + 8]);   af[3] = ldu32(&ah[(r0 + 8) * 136 + ko + 8]);
            alf[0] = ldu32(&al[r0 * 136 + ko]);      alf[1] = ldu32(&al[(r0 + 8) * 136 + ko]);
            alf[2] = ldu32(&al[r0 * 136 + ko + 8]);  alf[3] = ldu32(&al[(r0 + 8) * 136 + ko + 8]);
#pragma unroll
            for (int nt = 0; nt < 4; nt++) {
                int n = nq * 32 + nt * 8 + (lane >> 2);
                unsigned bh0 = ldu32(&wh[n * 136 + ko]), bh1 = ldu32(&wh[n * 136 + ko + 8]);
                unsigned bl0 = ldu32(&wl[n * 136 + ko]), bl1 = ldu32(&wl[n * 136 + ko + 8]);
                mma_bf16(acc[nt], af, bh0, bh1);
                mma_bf16(acc[nt], af, bl0, bl1);
                mma_bf16(acc[nt], alf, bh0, bh1);
            }
        }
    }

    float* out = (ny < 2) ? g_a : g_bv;
    const int colb = (ny & 1) * 128;
#pragma unroll
    for (int nt = 0; nt < 4; nt++) {
        int col = colb + nq * 32 + nt * 8 + 2 * (lane & 3);
        int r0 = growb + mg * 16 + (lane >> 2);
        *reinterpret_cast<float2*>(&out[r0 * INNER_ + col]) = make_float2(acc[nt][0], acc[nt][1]);
        *reinterpret_cast<float2*>(&out[(r0 + 8) * INNER_ + col]) = make_float2(acc[nt][2], acc[nt][3]);
    }
}

// =====================================================================
// Kernel 3: conv + silu + chunked parallel scan + b-gate.
// 400-thread blocks (16 ch x 25 chunks), 3 blocks/SM at regs=48.
// =====================================================================
__global__ __launch_bounds__(400) void k_convscan(const float* __restrict__ cw,
                                                  const float* __restrict__ cb,
                                                  const float* __restrict__ al,
                                                  const float* __restrict__ be,
                                                  const float* __restrict__ ga,
                                                  const float* __restrict__ de) {
    __shared__ float ends[25][16];
    const int t = threadIdx.x;
    const int ch = t & 15, ck = t >> 4;
    const int b = blockIdx.x >> 4;
    const int ig = blockIdx.x & 15;
    const int i = ig * 16 + ch;
    const int base = b * 125 * INNER_ + i;
    const int k0 = ck * 5;

    const float* w = cw + i * 5;
    const float w0 = w[0], w1 = w[1], w2 = w[2], w3 = w[3], w4 = w[4];
    const float bias = cb[i];
    const float siga = 1.f / (1.f + __expf(-al[i]));
    const float bb = be[i], gg = ga[i], dd = de[i];

    float av[9];
#pragma unroll
    for (int q = 0; q < 9; q++) {
        int kk = k0 - 2 + q;
        av[q] = (kk >= 0 && kk <= 124) ? g_a[base + kk * INNER_] : 0.f;
    }
    float bvv[5];
#pragma unroll
    for (int q = 0; q < 5; q++) bvv[q] = g_bv[base + (k0 + q) * INNER_];

    float tv[5];
    float s = 0.f;
#pragma unroll
    for (int q = 0; q < 5; q++) {
        float acc = bias;
        acc = fmaf(w0, av[q], acc);
        acc = fmaf(w1, av[q + 1], acc);
        acc = fmaf(w2, av[q + 2], acc);
        acc = fmaf(w3, av[q + 3], acc);
        acc = fmaf(w4, av[q + 4], acc);
        float u = acc / (1.f + __expf(-acc));
        s = fmaf(siga, s, bb * u);
        tv[q] = fmaf(gg, s, dd * u);
    }
    ends[ck][ch] = s;
    __syncthreads();

    float p2 = siga * siga, p4 = p2 * p2;
    float a5 = p4 * siga;
    float st = 0.f;
    for (int jj = 0; jj < ck; jj++)
        st = fmaf(a5, st, ends[jj][ch]);
    float gc = gg * st;

    float pw = siga;
#pragma unroll
    for (int q = 0; q < 5; q++) {
        g_u[base + (k0 + q) * INNER_] = fmaf(gc, pw, tv[q]) * bvv[q];
        pw *= siga;
    }
}

// =====================================================================
// Kernel 4: out-projection — full K=256 resident; 512 THREADS (16
// warps): at 165KB smem only 1 block fits per SM, so 8 warps left the
// SM latency-starved; 16 warps double the hiding with zero extra smem.
// Warp tile 16m x 16n (2 m-groups x 8 n-eighths). Four K-quarter
// commit groups + wait-ladder. Last layer: final rmsnorm folded.
// =====================================================================
__global__ __launch_bounds__(512) void k_outproj(int woff, const float* __restrict__ nfw) {
    extern __shared__ __align__(16) bf sm[];
    bf* ah = sm;             bf* al = sm + 8448;
    bf* wh = sm + 16896;     bf* wl = sm + 50688;
    const int t = threadIdx.x, lane = t & 31, w = t >> 5;
    const int mg = w >> 3, nq8 = w & 7;
    const int growb = blockIdx.x * 32;

    const unsigned whb = (unsigned)__cvta_generic_to_shared(wh);
    const unsigned wlb = (unsigned)__cvta_generic_to_shared(wl);

    // issue ALL W loads in 4 K-quarter groups (2048 chunks per group)
#pragma unroll
    for (int gsel = 0; gsel < 4; gsel++) {
#pragma unroll
        for (int q = 0; q < 4; q++) {
            int idx = t + 512 * q;
            int sl = idx >> 10;
            int c = idx & 1023;
            int row = c >> 3, k4 = (c & 7) + gsel * 8;
            cp16((sl ? wlb : whb) + row * 528 + k4 * 16,
                 (sl ? g_wbl : g_wbh) + woff + row * 256 + k4 * 8);
        }
        cp_commit();
    }
    // A: fp32 g_u -> split, plain stores (2048 float4 groups)
#pragma unroll
    for (int q = 0; q < 4; q++) {
        int idx = t + 512 * q;
        int row = idx >> 6, f4 = idx & 63;
        float4 v = *reinterpret_cast<const float4*>(&g_u[(growb + row) * INNER_ + f4 * 4]);
        bf h[4], l[4];
        split_bf(v.x, h[0], l[0]); split_bf(v.y, h[1], l[1]);
        split_bf(v.z, h[2], l[2]); split_bf(v.w, h[3], l[3]);
        *reinterpret_cast<ull*>(&ah[row * 264 + f4 * 4]) = *reinterpret_cast<ull*>(h);
        *reinterpret_cast<ull*>(&al[row * 264 + f4 * 4]) = *reinterpret_cast<ull*>(l);
    }

    float acc[2][4] = {};
#pragma unroll
    for (int qr = 0; qr < 4; qr++) {
        if (qr == 0) cp_waitg<3>();
        else if (qr == 1) cp_waitg<2>();
        else if (qr == 2) cp_waitg<1>();
        else cp_waitg<0>();
        __syncthreads();
#pragma unroll
        for (int ks2 = 0; ks2 < 4; ks2++) {
            int kst = qr * 4 + ks2;
            const int ko = kst * 16 + 2 * (lane & 3);
            const int r0 = mg * 16 + (lane >> 2);
            unsigned af[4], alf[4];
            af[0] = ldu32(&ah[r0 * 264 + ko]);       af[1] = ldu32(&ah[(r0 + 8) * 264 + ko]);
            af[2] = ldu32(&ah[r0 * 264 + ko + 8]);   af[3] = ldu32(&ah[(r0 + 8) * 264 + ko + 8]);
            alf[0] = ldu32(&al[r0 * 264 + ko]);      alf[1] = ldu32(&al[(r0 + 8) * 264 + ko]);
            alf[2] = ldu32(&al[r0 * 264 + ko + 8]);  alf[3] = ldu32(&al[(r0 + 8) * 264 + ko + 8]);
#pragma unroll
            for (int nt = 0; nt < 2; nt++) {
                int n = nq8 * 16 + nt * 8 + (lane >> 2);
                unsigned bh0 = ldu32(&wh[n * 264 + ko]), bh1 = ldu32(&wh[n * 264 + ko + 8]);
                unsigned bl0 = ldu32(&wl[n * 264 + ko]), bl1 = ldu32(&wl[n * 264 + ko + 8]);
                mma_bf16(acc[nt], af, bh0, bh1);
                mma_bf16(acc[nt], af, bl0, bl1);
                mma_bf16(acc[nt], alf, bh0, bh1);
            }
        }
    }
    __syncthreads();

    float (*hbuf)[132] = reinterpret_cast<float(*)[132]>(sm);
#pragma unroll
    for (int nt = 0; nt < 2; nt++) {
        int colw = nq8 * 16 + nt * 8 + 2 * (lane & 3);
        int r0 = mg * 16 + (lane >> 2);
        *reinterpret_cast<float2*>(&hbuf[r0][colw]) = make_float2(acc[nt][0], acc[nt][1]);
        *reinterpret_cast<float2*>(&hbuf[r0 + 8][colw]) = make_float2(acc[nt][2], acc[nt][3]);
    }
    __syncthreads();

    {
        int row = t >> 4, part = t & 15;        // 512 thr: 8 cols each
        int grow = growb + row;
        float ssq = 0.f;
#pragma unroll
        for (int j = 0; j < 8; j++) {
            int c = part * 8 + j;
            float nv = 2.f * g_h[grow * 128 + c] + hbuf[row][c];
            hbuf[row][c] = nv;
            ssq += nv * nv;
        }
        ssq += __shfl_xor_sync(0xffffffffu, ssq, 1);
        ssq += __shfl_xor_sync(0xffffffffu, ssq, 2);
        ssq += __shfl_xor_sync(0xffffffffu, ssq, 4);
        ssq += __shfl_xor_sync(0xffffffffu, ssq, 8);
        float sc = rsqrtf(ssq * (1.0f / 128.0f) + EPS_);
        if (part == 0) g_scale[grow] = sc;
        if (nfw == nullptr) {
#pragma unroll
            for (int j = 0; j < 8; j += 2) {
                int c = part * 8 + j;
                float v0 = hbuf[row][c], v1 = hbuf[row][c + 1];
                *reinterpret_cast<float2*>(&g_h[grow * 128 + c]) = make_float2(v0, v1);
                bf h0, l0, h1, l1;
                split_bf(v0 * sc, h0, l0); split_bf(v1 * sc, h1, l1);
                bf hp[2] = {h0, h1}, lp[2] = {l0, l1};
                *reinterpret_cast<unsigned*>(&g_nhh[grow * 128 + c]) = *reinterpret_cast<unsigned*>(hp);
                *reinterpret_cast<unsigned*>(&g_nhl[grow * 128 + c]) = *reinterpret_cast<unsigned*>(lp);
            }
        } else {
#pragma unroll
            for (int j = 0; j < 8; j += 2) {
                int c = part * 8 + j;
                float v0 = hbuf[row][c] * sc * nfw[c];
                float v1 = hbuf[row][c + 1] * sc * nfw[c + 1];
                bf h0, l0, h1, l1;
                split_bf(v0, h0, l0); split_bf(v1, h1, l1);
                bf hp[2] = {h0, h1}, lp[2] = {l0, l1};
                *reinterpret_cast<unsigned*>(&g_fhi[grow * 128 + c]) = *reinterpret_cast<unsigned*>(hp);
                *reinterpret_cast<unsigned*>(&g_flo[grow * 128 + c]) = *reinterpret_cast<unsigned*>(lp);
            }
        }
    }
}

// =====================================================================
// Kernel 5: final GEMM (bf16 hi/lo split MMA) — FROZEN R12 version:
// KS=50, static 41KB smem (~5 blocks/SM), depth-1 register weight
// prefetch, barrier-free mainloop.
// =====================================================================
__global__ __launch_bounds__(256) void k_final(const float* __restrict__ outW) {
    __shared__ __align__(16) bf fh[32][328];
    __shared__ __align__(16) bf fl[32][328];

    const int t = threadIdx.x;
    const int w = t >> 5, l = t & 31;
    const int g = l >> 2, tig = l & 3;
    const int obase = blockIdx.x * 128;
    const int ks = blockIdx.y;
    const int jbase = ks * 320;

    {
        unsigned fhb = (unsigned)__cvta_generic_to_shared(&fh[0][0]);
        unsigned flb = (unsigned)__cvta_generic_to_shared(&fl[0][0]);
#pragma unroll
        for (int q = 0; q < 5; q++) {
            int c = t + 256 * q;
            int b = c / 40, kc = c - b * 40;
            cp16(fhb + b * 656 + kc * 16, g_fhi + b * DNP_ + jbase + kc * 8);
            cp16(flb + b * 656 + kc * 16, g_flo + b * DNP_ + jbase + kc * 8);
        }
    }
    cp_commit();

    const int n0 = obase + w * 16 + g;
    const float* w0p = outW + (size_t)n0 * DNP_ + jbase + 2 * tig;
    const float* w1p = w0p + (size_t)8 * DNP_;

    float c[2][2][4];
#pragma unroll
    for (int mt = 0; mt < 2; mt++)
#pragma unroll
        for (int nt = 0; nt < 2; nt++)
#pragma unroll
            for (int q = 0; q < 4; q++) c[mt][nt][q] = 0.f;

    float2 cur[4] = { *reinterpret_cast<const float2*>(w0p),
                      *reinterpret_cast<const float2*>(w0p + 8),
                      *reinterpret_cast<const float2*>(w1p),
                      *reinterpret_cast<const float2*>(w1p + 8) };

    cp_waitall();
    __syncthreads();

    for (int ch = 0; ch < 20; ch++) {
        int chn = (ch + 1 < 20) ? (ch + 1) : 19;
        float2 nxt[4] = { *reinterpret_cast<const float2*>(w0p + chn * 16),
                          *reinterpret_cast<const float2*>(w0p + chn * 16 + 8),
                          *reinterpret_cast<const float2*>(w1p + chn * 16),
                          *reinterpret_cast<const float2*>(w1p + chn * 16 + 8) };

        const int off = ch * 16 + 2 * tig;
        unsigned ahi[2][4], alo[2][4];
#pragma unroll
        for (int mt = 0; mt < 2; mt++) {
            int r = g + mt * 16;
            ahi[mt][0] = ldu32(&fh[r][off]);
            ahi[mt][1] = ldu32(&fh[r + 8][off]);
            ahi[mt][2] = ldu32(&fh[r][off + 8]);
            ahi[mt][3] = ldu32(&fh[r + 8][off + 8]);
            alo[mt][0] = ldu32(&fl[r][off]);
            alo[mt][1] = ldu32(&fl[r + 8][off]);
            alo[mt][2] = ldu32(&fl[r][off + 8]);
            alo[mt][3] = ldu32(&fl[r + 8][off + 8]);
        }

        unsigned bhi[2][2], blo[2][2];
#pragma unroll
        for (int nt = 0; nt < 2; nt++) {
#pragma unroll
            for (int hb = 0; hb < 2; hb++) {
                float2 wv = cur[nt * 2 + hb];
                __nv_bfloat162 h2 = __floats2bfloat162_rn(wv.x, wv.y);
                float2 lo2 = make_float2(wv.x - __bfloat162float(__low2bfloat16(h2)),
                                         wv.y - __bfloat162float(__high2bfloat16(h2)));
                __nv_bfloat162 l2 = __floats2bfloat162_rn(lo2.x, lo2.y);
                bhi[nt][hb] = *reinterpret_cast<unsigned*>(&h2);
                blo[nt][hb] = *reinterpret_cast<unsigned*>(&l2);
            }
        }

#pragma unroll
        for (int mt = 0; mt < 2; mt++)
#pragma unroll
            for (int nt = 0; nt < 2; nt++) {
                mma_bf16(c[mt][nt], ahi[mt], bhi[nt][0], bhi[nt][1]);
                mma_bf16(c[mt][nt], ahi[mt], blo[nt][0], blo[nt][1]);
                mma_bf16(c[mt][nt], alo[mt], bhi[nt][0], bhi[nt][1]);
            }

#pragma unroll
        for (int q = 0; q < 4; q++) cur[q] = nxt[q];
    }

#pragma unroll
    for (int mt = 0; mt < 2; mt++)
#pragma unroll
        for (int nt = 0; nt < 2; nt++) {
            int o = obase + w * 16 + nt * 8 + 2 * tig;
            int b0i = g + mt * 16;
            float* p0 = &g_part[(ks * B_ + b0i) * CF_ + o];
            float* p1 = &g_part[(ks * B_ + b0i + 8) * CF_ + o];
            *reinterpret_cast<float2*>(p0) = make_float2(c[mt][nt][0], c[mt][nt][1]);
            *reinterpret_cast<float2*>(p1) = make_float2(c[mt][nt][2], c[mt][nt][3]);
        }
}

// Kernel 6: reduce split-K partials + bias -> d_out (float4 vectorized)
__global__ __launch_bounds__(256) void k_reduce(const float* __restrict__ outb,
                                                float* __restrict__ out) {
    int idx = blockIdx.x * 256 + threadIdx.x;   // 49152 = 192*256 exact
    int b = idx / 1536, oq = idx - b * 1536;    // CF/4 = 1536
    float4 v = *reinterpret_cast<const float4*>(&outb[oq * 4]);
#pragma unroll
    for (int s = 0; s < KS_; s++) {
        float4 p = *reinterpret_cast<const float4*>(&g_part[(s * B_ + b) * CF_ + oq * 4]);
        v.x += p.x; v.y += p.y; v.z += p.z; v.w += p.w;
    }
    *reinterpret_cast<float4*>(&out[b * CF_ + oq * 4]) = v;
}

// =====================================================================
extern "C" void kernel_launch(void* const* d_in, const int* in_sizes, int n_in,
                              void* d_out, int out_size) {
    const float* x     = (const float*)d_in[0];
    const float* peW   = (const float*)d_in[1];
    const float* peb   = (const float*)d_in[2];
    const float* normw = (const float*)d_in[3];
    const float* ipaW  = (const float*)d_in[4];
    const float* ipbW  = (const float*)d_in[5];
    const float* convW = (const float*)d_in[6];
    const float* convb = (const float*)d_in[7];
    const float* alp   = (const float*)d_in[8];
    const float* bet   = (const float*)d_in[9];
    const float* gam   = (const float*)d_in[10];
    const float* del   = (const float*)d_in[11];
    const float* opW   = (const float*)d_in[12];
    const float* normf = (const float*)d_in[13];
    const float* outW  = (const float*)d_in[14];
    const float* outb  = (const float*)d_in[15];
    float* out = (float*)d_out;

    cudaFuncSetAttribute(k_embed,   cudaFuncAttributeMaxDynamicSharedMemorySize, SM_EMB);
    cudaFuncSetAttribute(k_inproj,  cudaFuncAttributeMaxDynamicSharedMemorySize, SM_IP);
    cudaFuncSetAttribute(k_outproj, cudaFuncAttributeMaxDynamicSharedMemorySize, SM_OP);

    k_prep_all<<<(PREP_TOT + 255) / 256, 256>>>(peW, normw, ipaW, ipbW, opW);
    k_embed<<<M_ / 32, 256, SM_EMB>>>(x, peb);
    for (int l = 0; l < 4; l++) {
        int lb = WSZ_EMB + l * WSZ_LAYER;
        k_inproj<<<dim3(M_ / 32, 4), 256, SM_IP>>>(lb);
        k_convscan<<<B_ * 16, 400>>>(convW + l * INNER_ * 5, convb + l * INNER_,
                                     alp + l * INNER_, bet + l * INNER_,
                                     gam + l * INNER_, del + l * INNER_);
        k_outproj<<<M_ / 32, 512, SM_OP>>>(lb + 65536, (l == 3) ? normf : nullptr);
    }
    k_final<<<dim3(CF_ / 128, KS_), 256>>>(outW);
    k_reduce<<<(B_ * CF_) / 1024, 256>>>(outb, out);
}